// round 7
// baseline (speedup 1.0000x reference)
#include <cuda_runtime.h>
#include <cstdint>

#define BB 128
#define TT 784
#define HH 256
#define LL 20
#define CC 10

// Scratch (device globals: allocation-free per harness rules)
__device__ float g_xp[(size_t)BB * TT * HH];   // per-layer input projection [B*T, H]
__device__ float g_h [(size_t)BB * TT * HH];   // per-layer hidden output   [B*T, H]
__device__ int   g_prog[BB / 2];               // per-pair watermark: l*TT + t_done

// Dynamic smem layout:
//   scan CTAs: [0, 4608) h buffers (2 buf x 2 samples x 288 floats)
//              [4608, 4608 + 512*52*4) per-thread W spill regions
//   proj CTAs: [0, 8704) Ash 128x17, [8704, 17152) Bsh 16x132
#define SM_H_BYTES   4608
#define SM_W_STRIDE  52                         // floats per thread region (48 + pad)
#define SMEM_DYN     (SM_H_BYTES + 512 * SM_W_STRIDE * 4)   // 111104

// ---------------------------------------------------------------------------
// helpers
// ---------------------------------------------------------------------------
__device__ __forceinline__ void ffma2(float2& c, float2 a, float2 b) {
    union U { float2 f; unsigned long long u; };
    U A, Bv, C;
    A.f = a; Bv.f = b; C.f = c;
    asm("fma.rn.f32x2 %0, %1, %2, %3;"
        : "=l"(C.u) : "l"(A.u), "l"(Bv.u), "l"(C.u));
    c = C.f;
}

// ---------------------------------------------------------------------------
// Layer-0 projection + watermark reset: xp = x*W0 + b0 (I==1)
// ---------------------------------------------------------------------------
__global__ void proj0_kernel(const float* __restrict__ x,
                             const float* __restrict__ W0,
                             const float* __restrict__ b0) {
    int row = blockIdx.x;
    int j   = threadIdx.x;
    if (row < BB / 2 && j == 0) g_prog[row] = 0;   // replay-safe reset
    g_xp[(size_t)row * HH + j] = x[row] * W0[j] + b0[j];
}

// ---------------------------------------------------------------------------
// Fused layer kernel. Grid 148 x 512 threads.
//   CTAs [0,64):  recurrent scan of layer l (2 samples each, W regs+smem)
//   CTAs [64,148): projection GEMM h^l -> xp^{l+1}, watermark-gated
// ---------------------------------------------------------------------------
__global__ __launch_bounds__(512, 1)
void fused_layer(const float* __restrict__ Whh,
                 const float* __restrict__ bhh,
                 const float* __restrict__ Wih,
                 const float* __restrict__ bih,
                 int l, int do_proj) {
    extern __shared__ __align__(16) char smem_raw[];
    const int tid = threadIdx.x;

    if (blockIdx.x < 64) {
        // ================= SCAN =================
        float* sm_h = (float*)smem_raw;                         // [2][2][288]
        float* sm_w = (float*)(smem_raw + SM_H_BYTES);

        const int c  = blockIdx.x;        // pair id
        const int b0 = 2 * c, b1 = 2 * c + 1;
        const int jg = tid >> 3;          // 0..63 -> rows j4..j4+3
        const int kc = tid & 7;           // k-chunk 32
        const int j4 = jg * 4;
        const int k0 = kc * 32;

        const float* W = Whh + (size_t)l * HH * HH;

        // W rows j4+0, j4+1 fully in regs (16 f4); j4+2 first half (4 f4)
        float4 wr[20];
#pragma unroll
        for (int r = 0; r < 2; r++)
#pragma unroll
            for (int i = 0; i < 8; i++)
                wr[r * 8 + i] = *(const float4*)(W + (size_t)(j4 + r) * HH + k0 + 4 * i);
#pragma unroll
        for (int i = 0; i < 4; i++)
            wr[16 + i] = *(const float4*)(W + (size_t)(j4 + 2) * HH + k0 + 4 * i);

        // smem W: j4+2 second half (4 f4) + j4+3 (8 f4)
        float* myw = sm_w + tid * SM_W_STRIDE;
#pragma unroll
        for (int i = 0; i < 4; i++)
            *(float4*)(myw + 4 * i) =
                *(const float4*)(W + (size_t)(j4 + 2) * HH + k0 + 16 + 4 * i);
#pragma unroll
        for (int i = 0; i < 8; i++)
            *(float4*)(myw + 16 + 4 * i) =
                *(const float4*)(W + (size_t)(j4 + 3) * HH + k0 + 4 * i);

        float4 bj4 = make_float4(0.f, 0.f, 0.f, 0.f);
        if (kc == 0) bj4 = *(const float4*)(bhh + l * HH + j4);

        // zero h buffers
        for (int i = tid; i < 2 * 2 * 288; i += 512) sm_h[i] = 0.0f;
        __syncthreads();

        const float* xp0 = g_xp + ((size_t)b0 * TT) * HH + j4;
        const float* xp1 = g_xp + ((size_t)b1 * TT) * HH + j4;
        float*       ho0 = g_h  + ((size_t)b0 * TT) * HH + j4;
        float*       ho1 = g_h  + ((size_t)b1 * TT) * HH + j4;

        // h write slot for j4 (chunk stride 36 to de-conflict kc streams)
        const int wslot = (jg >> 3) * 36 + (jg & 7) * 4;
        const int rbase = kc * 36;

        int cur = 0;
        for (int t = 0; t < TT; t++) {
            float4 xv0, xv1;
            if (kc == 0) {
                xv0 = *(const float4*)xp0;  xv1 = *(const float4*)xp1;
                xp0 += HH; xp1 += HH;
            }

            const float* h0p = sm_h + cur * 576 + rbase;        // sample 0
            const float* h1p = sm_h + cur * 576 + 288 + rbase;  // sample 1

            float2 acc[4][2];
#pragma unroll
            for (int jj = 0; jj < 4; jj++) {
                acc[jj][0] = make_float2(0.f, 0.f);
                acc[jj][1] = make_float2(0.f, 0.f);
            }

#pragma unroll
            for (int i = 0; i < 8; i++) {
                float4 a = *(const float4*)(h0p + 4 * i);
                float4 b = *(const float4*)(h1p + 4 * i);
                float4 w0 = wr[i];
                float4 w1 = wr[8 + i];
                float4 w2 = (i < 4) ? wr[16 + i] : *(const float4*)(myw + (i - 4) * 4);
                float4 w3 = *(const float4*)(myw + 16 + 4 * i);

                ffma2(acc[0][0], make_float2(w0.x, w0.y), make_float2(a.x, a.y));
                ffma2(acc[0][0], make_float2(w0.z, w0.w), make_float2(a.z, a.w));
                ffma2(acc[0][1], make_float2(w0.x, w0.y), make_float2(b.x, b.y));
                ffma2(acc[0][1], make_float2(w0.z, w0.w), make_float2(b.z, b.w));

                ffma2(acc[1][0], make_float2(w1.x, w1.y), make_float2(a.x, a.y));
                ffma2(acc[1][0], make_float2(w1.z, w1.w), make_float2(a.z, a.w));
                ffma2(acc[1][1], make_float2(w1.x, w1.y), make_float2(b.x, b.y));
                ffma2(acc[1][1], make_float2(w1.z, w1.w), make_float2(b.z, b.w));

                ffma2(acc[2][0], make_float2(w2.x, w2.y), make_float2(a.x, a.y));
                ffma2(acc[2][0], make_float2(w2.z, w2.w), make_float2(a.z, a.w));
                ffma2(acc[2][1], make_float2(w2.x, w2.y), make_float2(b.x, b.y));
                ffma2(acc[2][1], make_float2(w2.z, w2.w), make_float2(b.z, b.w));

                ffma2(acc[3][0], make_float2(w3.x, w3.y), make_float2(a.x, a.y));
                ffma2(acc[3][0], make_float2(w3.z, w3.w), make_float2(a.z, a.w));
                ffma2(acc[3][1], make_float2(w3.x, w3.y), make_float2(b.x, b.y));
                ffma2(acc[3][1], make_float2(w3.z, w3.w), make_float2(b.z, b.w));
            }

            // horizontal + width-8 shfl reduce over kc lanes
            float v[4][2];
#pragma unroll
            for (int jj = 0; jj < 4; jj++) {
                v[jj][0] = acc[jj][0].x + acc[jj][0].y;
                v[jj][1] = acc[jj][1].x + acc[jj][1].y;
            }
#pragma unroll
            for (int off = 1; off < 8; off <<= 1)
#pragma unroll
                for (int jj = 0; jj < 4; jj++) {
                    v[jj][0] += __shfl_down_sync(0xffffffffu, v[jj][0], off, 8);
                    v[jj][1] += __shfl_down_sync(0xffffffffu, v[jj][1], off, 8);
                }

            int nxt = cur ^ 1;
            if (kc == 0) {
                float4 o0, o1;
                o0.x = fmaxf(xv0.x + bj4.x + v[0][0], 0.f);
                o0.y = fmaxf(xv0.y + bj4.y + v[1][0], 0.f);
                o0.z = fmaxf(xv0.z + bj4.z + v[2][0], 0.f);
                o0.w = fmaxf(xv0.w + bj4.w + v[3][0], 0.f);
                o1.x = fmaxf(xv1.x + bj4.x + v[0][1], 0.f);
                o1.y = fmaxf(xv1.y + bj4.y + v[1][1], 0.f);
                o1.z = fmaxf(xv1.z + bj4.z + v[2][1], 0.f);
                o1.w = fmaxf(xv1.w + bj4.w + v[3][1], 0.f);
                *(float4*)(sm_h + nxt * 576 + wslot)       = o0;
                *(float4*)(sm_h + nxt * 576 + 288 + wslot) = o1;
                *(float4*)ho0 = o0;
                *(float4*)ho1 = o1;
                ho0 += HH; ho1 += HH;
            }

            const bool pub = (((t + 1) & 63) == 0) || (t == TT - 1);
            if (pub) __threadfence();     // make this thread's h STGs gpu-visible
            __syncthreads();
            if (pub && tid == 0)
                ((volatile int*)g_prog)[c] = l * TT + t + 1;
            cur = nxt;
        }
    } else {
        // ================= PROJ (xp for layer l+1) =================
        if (!do_proj) return;
        float (*Ash)[17]  = (float(*)[17])smem_raw;
        float (*Bsh)[132] = (float(*)[132])(smem_raw + 8704);

        const float* Bw   = Wih + (size_t)l * HH * HH;
        const float* bias = bih + (size_t)l * HH;

        const int pid = blockIdx.x - 64;      // 0..83
        const int tx  = tid & 15;             // 8 cols each
        const int ty  = tid >> 4;             // 4 rows each

        for (int idx = pid; idx < 1568; idx += 84) {
            const int r0 = (idx >> 1) * 128;          // first row of tile
            const int cb = (idx & 1) * 128;           // first col

            // watermark gate (tile spans <= 2 samples)
            if (tid == 0) {
                int bf = r0 / TT, bl2 = (r0 + 127) / TT;
                int need1 = l * TT + min(TT, r0 + 128 - bf * TT);
                while (((volatile int*)g_prog)[bf >> 1] < need1) __nanosleep(100);
                if (bl2 != bf) {
                    int need2 = l * TT + (r0 + 128 - bl2 * TT);
                    while (((volatile int*)g_prog)[bl2 >> 1] < need2) __nanosleep(100);
                }
            }
            __syncthreads();
            __threadfence();                  // acquire: order h reads after flag

            float2 acc[4][4];
#pragma unroll
            for (int i = 0; i < 4; i++)
#pragma unroll
                for (int jp = 0; jp < 4; jp++) acc[i][jp] = make_float2(0.f, 0.f);

            for (int kt = 0; kt < HH; kt += 16) {
#pragma unroll
                for (int p = 0; p < 4; p++) {
                    int f = tid + p * 512;
                    int m = f >> 4, k = f & 15;
                    Ash[m][k] = g_h[(size_t)(r0 + m) * HH + kt + k];
                }
#pragma unroll
                for (int p = 0; p < 4; p++) {
                    int f = tid + p * 512;
                    int n = f >> 4, k = f & 15;
                    Bsh[k][n] = Bw[(size_t)(cb + n) * HH + kt + k];
                }
                __syncthreads();
#pragma unroll
                for (int kk = 0; kk < 16; kk++) {
                    float4 bv0 = *(const float4*)&Bsh[kk][tx * 8];
                    float4 bv1 = *(const float4*)&Bsh[kk][tx * 8 + 4];
                    float2 bp[4] = { {bv0.x, bv0.y}, {bv0.z, bv0.w},
                                     {bv1.x, bv1.y}, {bv1.z, bv1.w} };
#pragma unroll
                    for (int i = 0; i < 4; i++) {
                        float av = Ash[ty * 4 + i][kk];
                        float2 aa = {av, av};
#pragma unroll
                        for (int jp = 0; jp < 4; jp++)
                            ffma2(acc[i][jp], aa, bp[jp]);
                    }
                }
                __syncthreads();
            }

            float bj[8];
#pragma unroll
            for (int j = 0; j < 8; j++) bj[j] = bias[cb + tx * 8 + j];
#pragma unroll
            for (int i = 0; i < 4; i++) {
                int row = r0 + ty * 4 + i;
#pragma unroll
                for (int jp = 0; jp < 4; jp++) {
                    g_xp[(size_t)row * HH + cb + tx * 8 + 2 * jp]     = acc[i][jp].x + bj[2 * jp];
                    g_xp[(size_t)row * HH + cb + tx * 8 + 2 * jp + 1] = acc[i][jp].y + bj[2 * jp + 1];
                }
            }
        }
    }
}

// ---------------------------------------------------------------------------
// Final FC: out[b,c] = sum_k h[b,T-1,k]*W_fc[c,k] + b_fc[c]
// ---------------------------------------------------------------------------
__global__ void fc_kernel(const float* __restrict__ Wfc,
                          const float* __restrict__ bfc,
                          float* __restrict__ out) {
    int b   = blockIdx.x;
    int tid = threadIdx.x;
    __shared__ float red[8];
    float hv = g_h[((size_t)b * TT + (TT - 1)) * HH + tid];
#pragma unroll
    for (int c = 0; c < CC; c++) {
        float p = hv * Wfc[(size_t)c * HH + tid];
#pragma unroll
        for (int o = 16; o > 0; o >>= 1)
            p += __shfl_down_sync(0xffffffffu, p, o);
        if ((tid & 31) == 0) red[tid >> 5] = p;
        __syncthreads();
        if (tid == 0) {
            float s = 0.0f;
#pragma unroll
            for (int w = 0; w < 8; w++) s += red[w];
            out[b * CC + c] = s + bfc[c];
        }
        __syncthreads();
    }
}

// ---------------------------------------------------------------------------
extern "C" void kernel_launch(void* const* d_in, const int* in_sizes, int n_in,
                              void* d_out, int out_size) {
    const float* x      = (const float*)d_in[0];
    const float* W_ih0  = (const float*)d_in[1];
    const float* b_ih0  = (const float*)d_in[2];
    const float* W_ih   = (const float*)d_in[3];
    const float* b_ih   = (const float*)d_in[4];
    const float* W_hh   = (const float*)d_in[5];
    const float* b_hh   = (const float*)d_in[6];
    const float* W_fc   = (const float*)d_in[7];
    const float* b_fc   = (const float*)d_in[8];
    float*       out    = (float*)d_out;

    static int smem_set = 0;
    if (!smem_set) {
        cudaFuncSetAttribute(fused_layer,
                             cudaFuncAttributeMaxDynamicSharedMemorySize, SMEM_DYN);
        smem_set = 1;
    }

    proj0_kernel<<<BB * TT, HH>>>(x, W_ih0, b_ih0);

    for (int l = 0; l < LL; l++)
        fused_layer<<<148, 512, SMEM_DYN>>>(W_hh, b_hh, W_ih, b_ih,
                                            l, l < LL - 1 ? 1 : 0);

    fc_kernel<<<BB, HH>>>(W_fc, b_fc, out);
}

// round 8
// speedup vs baseline: 1.2540x; 1.2540x over previous
#include <cuda_runtime.h>
#include <cstdint>

#define BB 128
#define TT 784
#define HH 256
#define LL 20
#define CC 10

// Scratch (device globals: allocation-free per harness rules)
__device__ float g_xp[(size_t)BB * TT * HH];   // per-layer input projection [B*T, H]
__device__ float g_h [(size_t)BB * TT * HH];   // per-layer hidden output   [B*T, H]
__device__ int   g_prog[BB / 2];               // per-pair watermark: l*TT + t_done

// Dynamic smem layout:
//   scan CTAs: [0, 4608) h buffers (2 buf x 2 samples x 288 floats)
//              [4608, +512*68*4) per-thread W regions (64 fl data + 4 pad)
//   proj CTAs: [0, 8704) Ash 128x17, [8704, 17152) Bsh 16x132
#define SM_H_BYTES   4608
#define SM_W_STRIDE  68
#define SMEM_DYN     (SM_H_BYTES + 512 * SM_W_STRIDE * 4)   // 143872

// ---------------------------------------------------------------------------
__device__ __forceinline__ void ffma2(float2& c, float2 a, float2 b) {
    union U { float2 f; unsigned long long u; };
    U A, Bv, C;
    A.f = a; Bv.f = b; C.f = c;
    asm("fma.rn.f32x2 %0, %1, %2, %3;"
        : "=l"(C.u) : "l"(A.u), "l"(Bv.u), "l"(C.u));
    c = C.f;
}

// ---------------------------------------------------------------------------
// Layer-0 projection + watermark reset: xp = x*W0 + b0 (I==1)
// ---------------------------------------------------------------------------
__global__ void proj0_kernel(const float* __restrict__ x,
                             const float* __restrict__ W0,
                             const float* __restrict__ b0) {
    int row = blockIdx.x;
    int j   = threadIdx.x;
    if (row < BB / 2 && j == 0) g_prog[row] = 0;   // replay-safe reset
    g_xp[(size_t)row * HH + j] = x[row] * W0[j] + b0[j];
}

// ---------------------------------------------------------------------------
// Fused layer kernel. Grid 148 x 512 threads.
//   CTAs [0,64):  recurrent scan of layer l (2 samples each)
//   CTAs [64,148): projection GEMM h^l -> xp^{l+1}, watermark-gated
// ---------------------------------------------------------------------------
__global__ __launch_bounds__(512, 1)
void fused_layer(const float* __restrict__ Whh,
                 const float* __restrict__ bhh,
                 const float* __restrict__ Wih,
                 const float* __restrict__ bih,
                 int l, int do_proj) {
    extern __shared__ __align__(16) char smem_raw[];
    const int tid = threadIdx.x;

    if (blockIdx.x < 64) {
        // ================= SCAN =================
        // Thread (jq = tid>>3, kc = tid&7): outputs j4 = 4*jq .. +3,
        // k window [kc*32, +32). W rows j4+0,j4+1 in regs (16 f4),
        // rows j4+2,j4+3 in a private smem region (16 f4, stride 68 fl).
        // h chunks stored at kc*36 (36-fl stride): the 8 kc read streams hit
        // disjoint bank groups AND each warp's LDS.128 touches only 8
        // distinct 16B lines (4-lane broadcast) -> 1 wavefront per load.
        float* sm_h = (float*)smem_raw;                         // [2][2][288]
        float* sm_w = (float*)(smem_raw + SM_H_BYTES);

        const int c  = blockIdx.x;        // pair id
        const int b0 = 2 * c, b1 = 2 * c + 1;
        const int jq = tid >> 3;
        const int kc = tid & 7;
        const int j4 = jq * 4;
        const int k0 = kc * 32;

        const float* W = Whh + (size_t)l * HH * HH;

        float4 w0[8], w1[8];
#pragma unroll
        for (int i = 0; i < 8; i++) {
            w0[i] = *(const float4*)(W + (size_t)(j4 + 0) * HH + k0 + 4 * i);
            w1[i] = *(const float4*)(W + (size_t)(j4 + 1) * HH + k0 + 4 * i);
        }
        float* myw = sm_w + tid * SM_W_STRIDE;
#pragma unroll
        for (int i = 0; i < 8; i++) {
            *(float4*)(myw + 4 * i)      = *(const float4*)(W + (size_t)(j4 + 2) * HH + k0 + 4 * i);
            *(float4*)(myw + 32 + 4 * i) = *(const float4*)(W + (size_t)(j4 + 3) * HH + k0 + 4 * i);
        }

        float4 bj4 = make_float4(0.f, 0.f, 0.f, 0.f);
        if (kc == 0) bj4 = *(const float4*)(bhh + l * HH + j4);

        for (int i = tid; i < 2 * 2 * 288; i += 512) sm_h[i] = 0.0f;
        __syncthreads();

        const float* xp0 = g_xp + ((size_t)b0 * TT) * HH + j4;
        const float* xp1 = g_xp + ((size_t)b1 * TT) * HH + j4;
        float*       ho0 = g_h  + ((size_t)b0 * TT) * HH + j4;
        float*       ho1 = g_h  + ((size_t)b1 * TT) * HH + j4;

        // write slot for outputs j4..j4+3: chunk jq>>3, offset 4*(jq&7)
        const int wslot = (jq >> 3) * 36 + (jq & 7) * 4;
        const int rbase = kc * 36;

        int cur = 0;
        for (int t = 0; t < TT; t++) {
            float4 xv0, xv1;
            if (kc == 0) {
                xv0 = *(const float4*)xp0;  xv1 = *(const float4*)xp1;
                xp0 += HH; xp1 += HH;
            }

            const float* h0p = sm_h + cur * 576 + rbase;
            const float* h1p = sm_h + cur * 576 + 288 + rbase;

            float2 acc[4][2];
#pragma unroll
            for (int jj = 0; jj < 4; jj++) {
                acc[jj][0] = make_float2(0.f, 0.f);
                acc[jj][1] = make_float2(0.f, 0.f);
            }

#pragma unroll
            for (int i = 0; i < 8; i++) {
                float4 a  = *(const float4*)(h0p + 4 * i);      // broadcast
                float4 b  = *(const float4*)(h1p + 4 * i);      // broadcast
                float4 W2 = *(const float4*)(myw + 4 * i);      // private
                float4 W3 = *(const float4*)(myw + 32 + 4 * i); // private
                float4 R0 = w0[i], R1 = w1[i];

                ffma2(acc[0][0], make_float2(R0.x, R0.y), make_float2(a.x, a.y));
                ffma2(acc[0][0], make_float2(R0.z, R0.w), make_float2(a.z, a.w));
                ffma2(acc[0][1], make_float2(R0.x, R0.y), make_float2(b.x, b.y));
                ffma2(acc[0][1], make_float2(R0.z, R0.w), make_float2(b.z, b.w));

                ffma2(acc[1][0], make_float2(R1.x, R1.y), make_float2(a.x, a.y));
                ffma2(acc[1][0], make_float2(R1.z, R1.w), make_float2(a.z, a.w));
                ffma2(acc[1][1], make_float2(R1.x, R1.y), make_float2(b.x, b.y));
                ffma2(acc[1][1], make_float2(R1.z, R1.w), make_float2(b.z, b.w));

                ffma2(acc[2][0], make_float2(W2.x, W2.y), make_float2(a.x, a.y));
                ffma2(acc[2][0], make_float2(W2.z, W2.w), make_float2(a.z, a.w));
                ffma2(acc[2][1], make_float2(W2.x, W2.y), make_float2(b.x, b.y));
                ffma2(acc[2][1], make_float2(W2.z, W2.w), make_float2(b.z, b.w));

                ffma2(acc[3][0], make_float2(W3.x, W3.y), make_float2(a.x, a.y));
                ffma2(acc[3][0], make_float2(W3.z, W3.w), make_float2(a.z, a.w));
                ffma2(acc[3][1], make_float2(W3.x, W3.y), make_float2(b.x, b.y));
                ffma2(acc[3][1], make_float2(W3.z, W3.w), make_float2(b.z, b.w));
            }

            float v[4][2];
#pragma unroll
            for (int jj = 0; jj < 4; jj++) {
                v[jj][0] = acc[jj][0].x + acc[jj][0].y;
                v[jj][1] = acc[jj][1].x + acc[jj][1].y;
            }
#pragma unroll
            for (int off = 1; off < 8; off <<= 1)
#pragma unroll
                for (int jj = 0; jj < 4; jj++) {
                    v[jj][0] += __shfl_down_sync(0xffffffffu, v[jj][0], off, 8);
                    v[jj][1] += __shfl_down_sync(0xffffffffu, v[jj][1], off, 8);
                }

            int nxt = cur ^ 1;
            if (kc == 0) {
                float4 o0, o1;
                o0.x = fmaxf(xv0.x + bj4.x + v[0][0], 0.f);
                o0.y = fmaxf(xv0.y + bj4.y + v[1][0], 0.f);
                o0.z = fmaxf(xv0.z + bj4.z + v[2][0], 0.f);
                o0.w = fmaxf(xv0.w + bj4.w + v[3][0], 0.f);
                o1.x = fmaxf(xv1.x + bj4.x + v[0][1], 0.f);
                o1.y = fmaxf(xv1.y + bj4.y + v[1][1], 0.f);
                o1.z = fmaxf(xv1.z + bj4.z + v[2][1], 0.f);
                o1.w = fmaxf(xv1.w + bj4.w + v[3][1], 0.f);
                *(float4*)(sm_h + nxt * 576 + wslot)       = o0;
                *(float4*)(sm_h + nxt * 576 + 288 + wslot) = o1;
                *(float4*)ho0 = o0;
                *(float4*)ho1 = o1;
                ho0 += HH; ho1 += HH;
            }

            const bool pub = (((t + 1) & 63) == 0) || (t == TT - 1);
            if (pub && kc == 0) __threadfence();   // h STGs gpu-visible
            __syncthreads();
            if (pub && tid == 0)
                ((volatile int*)g_prog)[c] = l * TT + t + 1;
            cur = nxt;
        }
    } else {
        // ================= PROJ (xp for layer l+1) =================
        if (!do_proj) return;
        float (*Ash)[17]  = (float(*)[17])smem_raw;
        float (*Bsh)[132] = (float(*)[132])(smem_raw + 8704);

        const float* Bw   = Wih + (size_t)l * HH * HH;
        const float* bias = bih + (size_t)l * HH;

        const int pid = blockIdx.x - 64;      // 0..83
        const int tx  = tid & 15;             // 8 cols each
        const int ty  = tid >> 4;             // 4 rows each

        for (int idx = pid; idx < 1568; idx += 84) {
            const int r0 = (idx >> 1) * 128;
            const int cb = (idx & 1) * 128;

            if (tid == 0) {
                int bf = r0 / TT, bl2 = (r0 + 127) / TT;
                int need1 = l * TT + min(TT, r0 + 128 - bf * TT);
                while (((volatile int*)g_prog)[bf >> 1] < need1) __nanosleep(100);
                if (bl2 != bf) {
                    int need2 = l * TT + (r0 + 128 - bl2 * TT);
                    while (((volatile int*)g_prog)[bl2 >> 1] < need2) __nanosleep(100);
                }
            }
            __syncthreads();
            __threadfence();

            float2 acc[4][4];
#pragma unroll
            for (int i = 0; i < 4; i++)
#pragma unroll
                for (int jp = 0; jp < 4; jp++) acc[i][jp] = make_float2(0.f, 0.f);

            for (int kt = 0; kt < HH; kt += 16) {
#pragma unroll
                for (int p = 0; p < 4; p++) {
                    int f = tid + p * 512;
                    int m = f >> 4, k = f & 15;
                    Ash[m][k] = g_h[(size_t)(r0 + m) * HH + kt + k];
                }
#pragma unroll
                for (int p = 0; p < 4; p++) {
                    int f = tid + p * 512;
                    int n = f >> 4, k = f & 15;
                    Bsh[k][n] = Bw[(size_t)(cb + n) * HH + kt + k];
                }
                __syncthreads();
#pragma unroll
                for (int kk = 0; kk < 16; kk++) {
                    float4 bv0 = *(const float4*)&Bsh[kk][tx * 8];
                    float4 bv1 = *(const float4*)&Bsh[kk][tx * 8 + 4];
                    float2 bp[4] = { {bv0.x, bv0.y}, {bv0.z, bv0.w},
                                     {bv1.x, bv1.y}, {bv1.z, bv1.w} };
#pragma unroll
                    for (int i = 0; i < 4; i++) {
                        float av = Ash[ty * 4 + i][kk];
                        float2 aa = {av, av};
#pragma unroll
                        for (int jp = 0; jp < 4; jp++)
                            ffma2(acc[i][jp], aa, bp[jp]);
                    }
                }
                __syncthreads();
            }

            float bj[8];
#pragma unroll
            for (int j = 0; j < 8; j++) bj[j] = bias[cb + tx * 8 + j];
#pragma unroll
            for (int i = 0; i < 4; i++) {
                int row = r0 + ty * 4 + i;
#pragma unroll
                for (int jp = 0; jp < 4; jp++) {
                    g_xp[(size_t)row * HH + cb + tx * 8 + 2 * jp]     = acc[i][jp].x + bj[2 * jp];
                    g_xp[(size_t)row * HH + cb + tx * 8 + 2 * jp + 1] = acc[i][jp].y + bj[2 * jp + 1];
                }
            }
        }
    }
}

// ---------------------------------------------------------------------------
// Final FC: out[b,c] = sum_k h[b,T-1,k]*W_fc[c,k] + b_fc[c]
// ---------------------------------------------------------------------------
__global__ void fc_kernel(const float* __restrict__ Wfc,
                          const float* __restrict__ bfc,
                          float* __restrict__ out) {
    int b   = blockIdx.x;
    int tid = threadIdx.x;
    __shared__ float red[8];
    float hv = g_h[((size_t)b * TT + (TT - 1)) * HH + tid];
#pragma unroll
    for (int c = 0; c < CC; c++) {
        float p = hv * Wfc[(size_t)c * HH + tid];
#pragma unroll
        for (int o = 16; o > 0; o >>= 1)
            p += __shfl_down_sync(0xffffffffu, p, o);
        if ((tid & 31) == 0) red[tid >> 5] = p;
        __syncthreads();
        if (tid == 0) {
            float s = 0.0f;
#pragma unroll
            for (int w = 0; w < 8; w++) s += red[w];
            out[b * CC + c] = s + bfc[c];
        }
        __syncthreads();
    }
}

// ---------------------------------------------------------------------------
extern "C" void kernel_launch(void* const* d_in, const int* in_sizes, int n_in,
                              void* d_out, int out_size) {
    const float* x      = (const float*)d_in[0];
    const float* W_ih0  = (const float*)d_in[1];
    const float* b_ih0  = (const float*)d_in[2];
    const float* W_ih   = (const float*)d_in[3];
    const float* b_ih   = (const float*)d_in[4];
    const float* W_hh   = (const float*)d_in[5];
    const float* b_hh   = (const float*)d_in[6];
    const float* W_fc   = (const float*)d_in[7];
    const float* b_fc   = (const float*)d_in[8];
    float*       out    = (float*)d_out;

    static int smem_set = 0;
    if (!smem_set) {
        cudaFuncSetAttribute(fused_layer,
                             cudaFuncAttributeMaxDynamicSharedMemorySize, SMEM_DYN);
        smem_set = 1;
    }

    proj0_kernel<<<BB * TT, HH>>>(x, W_ih0, b_ih0);

    for (int l = 0; l < LL; l++)
        fused_layer<<<148, 512, SMEM_DYN>>>(W_hh, b_hh, W_ih, b_ih,
                                            l, l < LL - 1 ? 1 : 0);

    fc_kernel<<<BB, HH>>>(W_fc, b_fc, out);
}

// round 9
// speedup vs baseline: 2.0800x; 1.6587x over previous
#include <cuda_runtime.h>
#include <cstdint>

#define BB 128
#define TT 784
#define HH 256
#define LL 20
#define CC 10

#define NPAIR  64
#define CHUNK  112
#define NCHUNK 7                      // 7*112 = 784
#define NTASK  (LL * 2 * NPAIR)       // 2560
#define NCTA   147                    // odd stride -> scan/proj mix per CTA

// Scratch (device globals: allocation-free per harness rules)
__device__ float g_xp[(size_t)BB * TT * HH];   // xp of current layer  [B*T, H]
__device__ float g_h [(size_t)BB * TT * HH];   // h  of current layer  [B*T, H]
__device__ int   g_hprog[LL * NPAIR];          // scan progress (t steps done)
__device__ int   g_xprog[LL * NPAIR];          // xp rows available for layer l

// smem: scan: h[2][2][256] @0 (4096B) | per-thread W (256*84 fl) @4096
//       proj: Ash 128x17 @0 (8704B)   | Bsh 16x132 @8704 (8448B)
#define SM_W_OFF  4096
#define SM_W_STRIDE 84                 // floats; 21*16B -> conflict-free
#define SMEM_DYN  (SM_W_OFF + 256 * SM_W_STRIDE * 4)   // 90112

// ---------------------------------------------------------------------------
__device__ __forceinline__ void ffma2(float2& c, float2 a, float2 b) {
    union U { float2 f; unsigned long long u; };
    U A, Bv, C;
    A.f = a; Bv.f = b; C.f = c;
    asm("fma.rn.f32x2 %0, %1, %2, %3;"
        : "=l"(C.u) : "l"(A.u), "l"(Bv.u), "l"(C.u));
    c = C.f;
}

// ---------------------------------------------------------------------------
// Layer-0 projection + watermark reset: xp = x*W0 + b0 (I==1)
// ---------------------------------------------------------------------------
__global__ void proj0_kernel(const float* __restrict__ x,
                             const float* __restrict__ W0,
                             const float* __restrict__ b0) {
    int row = blockIdx.x;
    int j   = threadIdx.x;
    if (j == 0 && row < LL * NPAIR) {           // replay-safe reset
        g_hprog[row] = 0;
        g_xprog[row] = (row < NPAIR) ? TT : 0;  // layer-0 xp filled here
    }
    g_xp[(size_t)row * HH + j] = x[row] * W0[j] + b0[j];
}

// ---------------------------------------------------------------------------
// Persistent wavefront kernel. 147 CTAs x 256 threads.
// Task q = 128*l + 2*c (scan) / +1 (proj l->l+1). CTA k runs q = k, k+147,...
// in increasing q; all dependencies point to smaller q -> no deadlock.
// ---------------------------------------------------------------------------
__global__ __launch_bounds__(256, 1)
void wave_kernel(const float* __restrict__ Whh,
                 const float* __restrict__ bhh,
                 const float* __restrict__ Wih,
                 const float* __restrict__ bih) {
    extern __shared__ __align__(16) char smem_raw[];
    const int tid = threadIdx.x;

    for (int q = blockIdx.x; q < NTASK; q += NCTA) {
        const int l = q >> 7;          // q / 128
        const int r = q & 127;
        const int c = r >> 1;          // pair id 0..63

        if ((r & 1) == 0) {
            // ===================== SCAN(l, c) =====================
            // 2 samples; thread j owns output col j over full k.
            // W row j: 44 float4 in regs + 20 float4 in private smem.
            float* sm_h = (float*)smem_raw;                 // [2][2][256]
            float* myw  = (float*)(smem_raw + SM_W_OFF) + tid * SM_W_STRIDE;

            const int b0 = 2 * c, b1 = 2 * c + 1;
            const int j  = tid;

            const float* Wrow = Whh + ((size_t)l * HH + j) * HH;
            float4 wr[44];
#pragma unroll
            for (int i = 0; i < 44; i++)
                wr[i] = *(const float4*)(Wrow + 4 * i);
#pragma unroll
            for (int i = 0; i < 20; i++)
                *(float4*)(myw + 4 * i) = *(const float4*)(Wrow + 176 + 4 * i);

            const float bj = bhh[l * HH + j];

            for (int i = tid; i < 1024; i += 256) ((float*)sm_h)[i] = 0.0f;
            __syncthreads();

            const float* xp0 = g_xp + (size_t)b0 * TT * HH + j;
            const float* xp1 = g_xp + (size_t)b1 * TT * HH + j;
            float*       ho0 = g_h  + (size_t)b0 * TT * HH + j;
            float*       ho1 = g_h  + (size_t)b1 * TT * HH + j;

            int cur = 0;
            for (int ch = 0; ch < NCHUNK; ch++) {
                // gate: xp rows for this chunk ready (preset TT for l==0)
                if (tid == 0) {
                    const int need = (ch + 1) * CHUNK;
                    while (((volatile int*)g_xprog)[l * NPAIR + c] < need)
                        __nanosleep(200);
                }
                __syncthreads();
                __threadfence();   // acquire: order xp reads after flag

#pragma unroll 1
                for (int tt = 0; tt < CHUNK; tt++) {
                    float xv0 = *xp0;  xp0 += HH;   // issued early, used late
                    float xv1 = *xp1;  xp1 += HH;

                    const float* hb0 = sm_h + cur * 512;
                    const float* hb1 = hb0 + 256;

                    float2 a0 = {0.f, 0.f}, b0v = {0.f, 0.f};
                    float2 a1 = {0.f, 0.f}, b1v = {0.f, 0.f};
#pragma unroll
                    for (int i = 0; i < 64; i++) {
                        float4 h0 = *(const float4*)(hb0 + 4 * i);  // broadcast
                        float4 h1 = *(const float4*)(hb1 + 4 * i);  // broadcast
                        float4 w  = (i < 44) ? wr[i]
                                             : *(const float4*)(myw + 4 * (i - 44));
                        ffma2(a0,  make_float2(w.x, w.y), make_float2(h0.x, h0.y));
                        ffma2(b0v, make_float2(w.z, w.w), make_float2(h0.z, h0.w));
                        ffma2(a1,  make_float2(w.x, w.y), make_float2(h1.x, h1.y));
                        ffma2(b1v, make_float2(w.z, w.w), make_float2(h1.z, h1.w));
                    }
                    float s0 = (a0.x + a0.y) + (b0v.x + b0v.y);
                    float s1 = (a1.x + a1.y) + (b1v.x + b1v.y);

                    float o0 = fmaxf(xv0 + bj + s0, 0.0f);
                    float o1 = fmaxf(xv1 + bj + s1, 0.0f);

                    int nxt = cur ^ 1;
                    sm_h[nxt * 512 + j]       = o0;
                    sm_h[nxt * 512 + 256 + j] = o1;
                    *ho0 = o0;  ho0 += HH;
                    *ho1 = o1;  ho1 += HH;
                    __syncthreads();   // h(t) ready for step t+1
                    cur = nxt;
                }

                // publish h progress (all threads' STGs fenced, then flag)
                __threadfence();
                __syncthreads();
                if (tid == 0)
                    ((volatile int*)g_hprog)[l * NPAIR + c] = (ch + 1) * CHUNK;
            }
        } else if (l < LL - 1) {
            // ===================== PROJ(l, c): h^l -> xp^{l+1} =====================
            float (*Ash)[17]  = (float(*)[17])smem_raw;
            float (*Bsh)[132] = (float(*)[132])(smem_raw + 8704);

            const float* Bw   = Wih + (size_t)l * HH * HH;
            const float* bias = bih + (size_t)l * HH;

            const int tx = tid & 15;      // 8 cols each
            const int ty = tid >> 4;      // 8 rows each

            for (int ch = 0; ch < NCHUNK; ch++) {
                if (tid == 0) {
                    const int need = (ch + 1) * CHUNK;
                    while (((volatile int*)g_hprog)[l * NPAIR + c] < need)
                        __nanosleep(200);
                }
                __syncthreads();
                __threadfence();   // acquire: order h reads after flag

#pragma unroll 1
                for (int sub = 0; sub < 4; sub++) {
                    const int s  = sub >> 1;                       // sample
                    const int cb = (sub & 1) * 128;                // col tile
                    const size_t rowbase = (size_t)(2 * c + s) * TT + ch * CHUNK;

                    float2 acc[8][4];
#pragma unroll
                    for (int i = 0; i < 8; i++)
#pragma unroll
                        for (int jp = 0; jp < 4; jp++) acc[i][jp] = make_float2(0.f, 0.f);

                    for (int kt = 0; kt < HH; kt += 16) {
#pragma unroll
                        for (int p = 0; p < 8; p++) {
                            int f = tid + p * 256;
                            int m = f >> 4, k = f & 15;
                            Ash[m][k] = (m < CHUNK)
                                ? g_h[(rowbase + m) * HH + kt + k] : 0.0f;
                        }
#pragma unroll
                        for (int p = 0; p < 8; p++) {
                            int f = tid + p * 256;
                            int n = f >> 4, k = f & 15;
                            Bsh[k][n] = Bw[(size_t)(cb + n) * HH + kt + k];
                        }
                        __syncthreads();
#pragma unroll
                        for (int kk = 0; kk < 16; kk++) {
                            float4 bv0 = *(const float4*)&Bsh[kk][tx * 8];
                            float4 bv1 = *(const float4*)&Bsh[kk][tx * 8 + 4];
                            float2 bp[4] = { {bv0.x, bv0.y}, {bv0.z, bv0.w},
                                             {bv1.x, bv1.y}, {bv1.z, bv1.w} };
#pragma unroll
                            for (int i = 0; i < 8; i++) {
                                float av = Ash[ty * 8 + i][kk];
                                float2 aa = {av, av};
#pragma unroll
                                for (int jp = 0; jp < 4; jp++)
                                    ffma2(acc[i][jp], aa, bp[jp]);
                            }
                        }
                        __syncthreads();
                    }

                    float bj[8];
#pragma unroll
                    for (int jj = 0; jj < 8; jj++) bj[jj] = bias[cb + tx * 8 + jj];
#pragma unroll
                    for (int i = 0; i < 8; i++) {
                        int m = ty * 8 + i;
                        if (m < CHUNK) {
#pragma unroll
                            for (int jp = 0; jp < 4; jp++) {
                                g_xp[(rowbase + m) * HH + cb + tx * 8 + 2 * jp]     = acc[i][jp].x + bj[2 * jp];
                                g_xp[(rowbase + m) * HH + cb + tx * 8 + 2 * jp + 1] = acc[i][jp].y + bj[2 * jp + 1];
                            }
                        }
                    }
                }

                // publish xp progress for layer l+1 (also releases the g_h
                // WAR hazard: scan(l+1,c) may now overwrite h rows of chunk ch)
                __threadfence();
                __syncthreads();
                if (tid == 0)
                    ((volatile int*)g_xprog)[(l + 1) * NPAIR + c] = (ch + 1) * CHUNK;
            }
        }
        __syncthreads();   // smem reuse barrier between tasks
    }
}

// ---------------------------------------------------------------------------
// Final FC: out[b,c] = sum_k h[b,T-1,k]*W_fc[c,k] + b_fc[c]
// ---------------------------------------------------------------------------
__global__ void fc_kernel(const float* __restrict__ Wfc,
                          const float* __restrict__ bfc,
                          float* __restrict__ out) {
    int b   = blockIdx.x;
    int tid = threadIdx.x;
    __shared__ float red[8];
    float hv = g_h[((size_t)b * TT + (TT - 1)) * HH + tid];
#pragma unroll
    for (int c = 0; c < CC; c++) {
        float p = hv * Wfc[(size_t)c * HH + tid];
#pragma unroll
        for (int o = 16; o > 0; o >>= 1)
            p += __shfl_down_sync(0xffffffffu, p, o);
        if ((tid & 31) == 0) red[tid >> 5] = p;
        __syncthreads();
        if (tid == 0) {
            float s = 0.0f;
#pragma unroll
            for (int w = 0; w < 8; w++) s += red[w];
            out[b * CC + c] = s + bfc[c];
        }
        __syncthreads();
    }
}

// ---------------------------------------------------------------------------
extern "C" void kernel_launch(void* const* d_in, const int* in_sizes, int n_in,
                              void* d_out, int out_size) {
    const float* x      = (const float*)d_in[0];
    const float* W_ih0  = (const float*)d_in[1];
    const float* b_ih0  = (const float*)d_in[2];
    const float* W_ih   = (const float*)d_in[3];
    const float* b_ih   = (const float*)d_in[4];
    const float* W_hh   = (const float*)d_in[5];
    const float* b_hh   = (const float*)d_in[6];
    const float* W_fc   = (const float*)d_in[7];
    const float* b_fc   = (const float*)d_in[8];
    float*       out    = (float*)d_out;

    static int smem_set = 0;
    if (!smem_set) {
        cudaFuncSetAttribute(wave_kernel,
                             cudaFuncAttributeMaxDynamicSharedMemorySize, SMEM_DYN);
        smem_set = 1;
    }

    proj0_kernel<<<BB * TT, HH>>>(x, W_ih0, b_ih0);
    wave_kernel<<<NCTA, 256, SMEM_DYN>>>(W_hh, b_hh, W_ih, b_ih);
    fc_kernel<<<BB, HH>>>(W_fc, b_fc, out);
}

// round 10
// speedup vs baseline: 2.6533x; 1.2757x over previous
#include <cuda_runtime.h>
#include <cstdint>

#define BB 128
#define TT 784
#define HH 256
#define LL 20
#define CC 10

#define NPAIR  64
#define CHUNK  112
#define NCHUNK 7                      // 7*112 = 784
#define NTASK  (LL * 2 * NPAIR)       // 2560
#define NCTA   147

// Scratch (device globals: allocation-free per harness rules)
__device__ float g_xp[(size_t)BB * TT * HH];
__device__ float g_h [(size_t)BB * TT * HH];
__device__ int   g_hprog[LL * NPAIR];          // scan progress (t steps done)
__device__ int   g_xprog[LL * NPAIR];          // xp rows available for layer l

// scan smem: h buffers [2 buf][2 samples][260 fl] = 4160B, then per-thread W
// (24 f4 data + 1 f4 pad = 100 fl stride). proj smem: Ash/Bsh as before.
#define SAMP_STRIDE 260               // 256 + 4 pad between kh halves
#define BUF_STRIDE  (2 * SAMP_STRIDE) // 520
#define SM_W_OFF    4160
#define SM_W_STRIDE 100
#define SMEM_DYN    (SM_W_OFF + 256 * SM_W_STRIDE * 4)   // 106560

// ---------------------------------------------------------------------------
__device__ __forceinline__ void ffma2(float2& c, float2 a, float2 b) {
    union U { float2 f; unsigned long long u; };
    U A, Bv, C;
    A.f = a; Bv.f = b; C.f = c;
    asm("fma.rn.f32x2 %0, %1, %2, %3;"
        : "=l"(C.u) : "l"(A.u), "l"(Bv.u), "l"(C.u));
    c = C.f;
}

// ---------------------------------------------------------------------------
// Layer-0 projection + watermark reset: xp = x*W0 + b0 (I==1)
// ---------------------------------------------------------------------------
__global__ void proj0_kernel(const float* __restrict__ x,
                             const float* __restrict__ W0,
                             const float* __restrict__ b0) {
    int row = blockIdx.x;
    int j   = threadIdx.x;
    if (j == 0 && row < LL * NPAIR) {           // replay-safe reset
        g_hprog[row] = 0;
        g_xprog[row] = (row < NPAIR) ? TT : 0;  // layer-0 xp filled here
    }
    g_xp[(size_t)row * HH + j] = x[row] * W0[j] + b0[j];
}

// ---------------------------------------------------------------------------
// Persistent wavefront kernel. 147 CTAs x 256 threads.
// Task q = 128*l + 2*c (scan) / +1 (proj l->l+1). CTA k runs q = k, k+147,...
// in increasing q; all dependencies point to smaller q -> no deadlock.
// ---------------------------------------------------------------------------
__global__ __launch_bounds__(256, 1)
void wave_kernel(const float* __restrict__ Whh,
                 const float* __restrict__ bhh,
                 const float* __restrict__ Wih,
                 const float* __restrict__ bih) {
    extern __shared__ __align__(16) char smem_raw[];
    const int tid = threadIdx.x;

    for (int q = blockIdx.x; q < NTASK; q += NCTA) {
        const int l = q >> 7;
        const int r = q & 127;
        const int c = r >> 1;

        if ((r & 1) == 0) {
            // ===================== SCAN(l, c) =====================
            // Thread (j2 = tid>>1, kh = tid&1): output cols c0=2*j2, c1=c0+1
            // over k in [kh*128, +128). W: 40 f4 regs + 24 f4 private smem.
            // h layout: [buf][sample][k + (k>=128 ? 4 : 0)] so the two kh
            // read-streams hit disjoint bank groups (1 wavefront per LDS).
            float* sm_h = (float*)smem_raw;
            float* myw  = (float*)(smem_raw + SM_W_OFF) + tid * SM_W_STRIDE;

            const int b0 = 2 * c, b1 = 2 * c + 1;
            const int j2 = tid >> 1;
            const int kh = tid & 1;
            const int c0 = 2 * j2;
            const int k0 = kh * 128;

            const float* W0r = Whh + ((size_t)l * HH + c0) * HH + k0;
            const float* W1r = W0r + HH;

            float4 wr[40];
#pragma unroll
            for (int i = 0; i < 32; i++) wr[i] = *(const float4*)(W0r + 4 * i);
#pragma unroll
            for (int i = 0; i < 8; i++)  wr[32 + i] = *(const float4*)(W1r + 4 * i);
#pragma unroll
            for (int i = 0; i < 24; i++)
                *(float4*)(myw + 4 * i) = *(const float4*)(W1r + 32 + 4 * i);

            float2 bj = make_float2(0.f, 0.f);
            if (kh == 0) bj = *(const float2*)(bhh + l * HH + c0);

            for (int i = tid; i < 2 * BUF_STRIDE; i += 256) sm_h[i] = 0.0f;
            __syncthreads();

            const float* xp0 = g_xp + (size_t)b0 * TT * HH + c0;
            const float* xp1 = g_xp + (size_t)b1 * TT * HH + c0;
            float*       ho0 = g_h  + (size_t)b0 * TT * HH + c0;
            float*       ho1 = g_h  + (size_t)b1 * TT * HH + c0;

            const int rdo   = kh * 132;                       // read base in sample
            const int wslot = c0 + (c0 >= 128 ? 4 : 0);       // write offset

            int cur = 0;
            for (int ch = 0; ch < NCHUNK; ch++) {
                if (tid == 0) {
                    const int need = (ch + 1) * CHUNK;
                    while (((volatile int*)g_xprog)[l * NPAIR + c] < need)
                        __nanosleep(200);
                }
                __syncthreads();
                __threadfence();   // acquire: order xp reads after flag

#pragma unroll 1
                for (int tt = 0; tt < CHUNK; tt++) {
                    float2 xv0, xv1;
                    if (kh == 0) {
                        xv0 = *(const float2*)xp0;
                        xv1 = *(const float2*)xp1;
                    }
                    xp0 += HH; xp1 += HH;

                    const float* hb0 = sm_h + cur * BUF_STRIDE + rdo;
                    const float* hb1 = hb0 + SAMP_STRIDE;

                    float2 aA[2][2], aB[2][2];   // [row][sample]
#pragma unroll
                    for (int rr = 0; rr < 2; rr++)
#pragma unroll
                        for (int s = 0; s < 2; s++) {
                            aA[rr][s] = make_float2(0.f, 0.f);
                            aB[rr][s] = make_float2(0.f, 0.f);
                        }

#pragma unroll
                    for (int i = 0; i < 32; i++) {
                        float4 h0 = *(const float4*)(hb0 + 4 * i);  // bcast
                        float4 h1 = *(const float4*)(hb1 + 4 * i);  // bcast
                        float4 w0 = wr[i];
                        float4 w1 = (i < 8) ? wr[32 + i]
                                            : *(const float4*)(myw + 4 * (i - 8));
                        ffma2(aA[0][0], make_float2(w0.x, w0.y), make_float2(h0.x, h0.y));
                        ffma2(aB[0][0], make_float2(w0.z, w0.w), make_float2(h0.z, h0.w));
                        ffma2(aA[0][1], make_float2(w0.x, w0.y), make_float2(h1.x, h1.y));
                        ffma2(aB[0][1], make_float2(w0.z, w0.w), make_float2(h1.z, h1.w));
                        ffma2(aA[1][0], make_float2(w1.x, w1.y), make_float2(h0.x, h0.y));
                        ffma2(aB[1][0], make_float2(w1.z, w1.w), make_float2(h0.z, h0.w));
                        ffma2(aA[1][1], make_float2(w1.x, w1.y), make_float2(h1.x, h1.y));
                        ffma2(aB[1][1], make_float2(w1.z, w1.w), make_float2(h1.z, h1.w));
                    }

                    float v[2][2];
#pragma unroll
                    for (int rr = 0; rr < 2; rr++)
#pragma unroll
                        for (int s = 0; s < 2; s++) {
                            float t2 = (aA[rr][s].x + aA[rr][s].y)
                                     + (aB[rr][s].x + aB[rr][s].y);
                            // combine kh=0 / kh=1 partials (adjacent lanes)
                            t2 += __shfl_down_sync(0xffffffffu, t2, 1, 2);
                            v[rr][s] = t2;
                        }

                    int nxt = cur ^ 1;
                    if (kh == 0) {
                        float2 o0, o1;
                        o0.x = fmaxf(xv0.x + bj.x + v[0][0], 0.f);
                        o0.y = fmaxf(xv0.y + bj.y + v[1][0], 0.f);
                        o1.x = fmaxf(xv1.x + bj.x + v[0][1], 0.f);
                        o1.y = fmaxf(xv1.y + bj.y + v[1][1], 0.f);
                        *(float2*)(sm_h + nxt * BUF_STRIDE + wslot)               = o0;
                        *(float2*)(sm_h + nxt * BUF_STRIDE + SAMP_STRIDE + wslot) = o1;
                        *(float2*)ho0 = o0;
                        *(float2*)ho1 = o1;
                    }
                    ho0 += HH; ho1 += HH;
                    __syncthreads();   // h(t) ready for step t+1
                    cur = nxt;
                }

                // publish h progress (each thread fences its own STGs)
                __threadfence();
                __syncthreads();
                if (tid == 0)
                    ((volatile int*)g_hprog)[l * NPAIR + c] = (ch + 1) * CHUNK;
            }
        } else if (l < LL - 1) {
            // ===================== PROJ(l, c): h^l -> xp^{l+1} =====================
            float (*Ash)[17]  = (float(*)[17])smem_raw;
            float (*Bsh)[132] = (float(*)[132])(smem_raw + 8704);

            const float* Bw   = Wih + (size_t)l * HH * HH;
            const float* bias = bih + (size_t)l * HH;

            const int tx = tid & 15;      // 8 cols each
            const int ty = tid >> 4;      // 8 rows each

            for (int ch = 0; ch < NCHUNK; ch++) {
                if (tid == 0) {
                    const int need = (ch + 1) * CHUNK;
                    while (((volatile int*)g_hprog)[l * NPAIR + c] < need)
                        __nanosleep(200);
                }
                __syncthreads();
                __threadfence();   // acquire: order h reads after flag

#pragma unroll 1
                for (int sub = 0; sub < 4; sub++) {
                    const int s  = sub >> 1;
                    const int cb = (sub & 1) * 128;
                    const size_t rowbase = (size_t)(2 * c + s) * TT + ch * CHUNK;

                    float2 acc[8][4];
#pragma unroll
                    for (int i = 0; i < 8; i++)
#pragma unroll
                        for (int jp = 0; jp < 4; jp++) acc[i][jp] = make_float2(0.f, 0.f);

                    for (int kt = 0; kt < HH; kt += 16) {
#pragma unroll
                        for (int p = 0; p < 8; p++) {
                            int f = tid + p * 256;
                            int m = f >> 4, k = f & 15;
                            Ash[m][k] = (m < CHUNK)
                                ? g_h[(rowbase + m) * HH + kt + k] : 0.0f;
                        }
#pragma unroll
                        for (int p = 0; p < 8; p++) {
                            int f = tid + p * 256;
                            int n = f >> 4, k = f & 15;
                            Bsh[k][n] = Bw[(size_t)(cb + n) * HH + kt + k];
                        }
                        __syncthreads();
#pragma unroll
                        for (int kk = 0; kk < 16; kk++) {
                            float4 bv0 = *(const float4*)&Bsh[kk][tx * 8];
                            float4 bv1 = *(const float4*)&Bsh[kk][tx * 8 + 4];
                            float2 bp[4] = { {bv0.x, bv0.y}, {bv0.z, bv0.w},
                                             {bv1.x, bv1.y}, {bv1.z, bv1.w} };
#pragma unroll
                            for (int i = 0; i < 8; i++) {
                                float av = Ash[ty * 8 + i][kk];
                                float2 aa = {av, av};
#pragma unroll
                                for (int jp = 0; jp < 4; jp++)
                                    ffma2(acc[i][jp], aa, bp[jp]);
                            }
                        }
                        __syncthreads();
                    }

                    float bj[8];
#pragma unroll
                    for (int jj = 0; jj < 8; jj++) bj[jj] = bias[cb + tx * 8 + jj];
#pragma unroll
                    for (int i = 0; i < 8; i++) {
                        int m = ty * 8 + i;
                        if (m < CHUNK) {
#pragma unroll
                            for (int jp = 0; jp < 4; jp++) {
                                g_xp[(rowbase + m) * HH + cb + tx * 8 + 2 * jp]     = acc[i][jp].x + bj[2 * jp];
                                g_xp[(rowbase + m) * HH + cb + tx * 8 + 2 * jp + 1] = acc[i][jp].y + bj[2 * jp + 1];
                            }
                        }
                    }
                }

                // publish xp progress for layer l+1 (also releases the g_h
                // WAR hazard for scan(l+1,c))
                __threadfence();
                __syncthreads();
                if (tid == 0)
                    ((volatile int*)g_xprog)[(l + 1) * NPAIR + c] = (ch + 1) * CHUNK;
            }
        }
        __syncthreads();   // smem reuse barrier between tasks
    }
}

// ---------------------------------------------------------------------------
// Final FC: out[b,c] = sum_k h[b,T-1,k]*W_fc[c,k] + b_fc[c]
// ---------------------------------------------------------------------------
__global__ void fc_kernel(const float* __restrict__ Wfc,
                          const float* __restrict__ bfc,
                          float* __restrict__ out) {
    int b   = blockIdx.x;
    int tid = threadIdx.x;
    __shared__ float red[8];
    float hv = g_h[((size_t)b * TT + (TT - 1)) * HH + tid];
#pragma unroll
    for (int c = 0; c < CC; c++) {
        float p = hv * Wfc[(size_t)c * HH + tid];
#pragma unroll
        for (int o = 16; o > 0; o >>= 1)
            p += __shfl_down_sync(0xffffffffu, p, o);
        if ((tid & 31) == 0) red[tid >> 5] = p;
        __syncthreads();
        if (tid == 0) {
            float s = 0.0f;
#pragma unroll
            for (int w = 0; w < 8; w++) s += red[w];
            out[b * CC + c] = s + bfc[c];
        }
        __syncthreads();
    }
}

// ---------------------------------------------------------------------------
extern "C" void kernel_launch(void* const* d_in, const int* in_sizes, int n_in,
                              void* d_out, int out_size) {
    const float* x      = (const float*)d_in[0];
    const float* W_ih0  = (const float*)d_in[1];
    const float* b_ih0  = (const float*)d_in[2];
    const float* W_ih   = (const float*)d_in[3];
    const float* b_ih   = (const float*)d_in[4];
    const float* W_hh   = (const float*)d_in[5];
    const float* b_hh   = (const float*)d_in[6];
    const float* W_fc   = (const float*)d_in[7];
    const float* b_fc   = (const float*)d_in[8];
    float*       out    = (float*)d_out;

    static int smem_set = 0;
    if (!smem_set) {
        cudaFuncSetAttribute(wave_kernel,
                             cudaFuncAttributeMaxDynamicSharedMemorySize, SMEM_DYN);
        smem_set = 1;
    }

    proj0_kernel<<<BB * TT, HH>>>(x, W_ih0, b_ih0);
    wave_kernel<<<NCTA, 256, SMEM_DYN>>>(W_hh, b_hh, W_ih, b_ih);
    fc_kernel<<<BB, HH>>>(W_fc, b_fc, out);
}

// round 11
// speedup vs baseline: 2.8610x; 1.0783x over previous
#include <cuda_runtime.h>
#include <cstdint>

#define BB 128
#define TT 784
#define HH 256
#define LL 20
#define CC 10

#define NQUAD  32                     // 4 samples per scan task
#define CHUNK  112
#define NCHUNK 7                      // 7*112 = 784
#define NTASK  (LL * 2 * NQUAD)       // 1280
#define NCTA   147

// Scratch (device globals: allocation-free per harness rules)
__device__ float g_xp[(size_t)BB * TT * HH];
__device__ float g_h [(size_t)BB * TT * HH];
__device__ int   g_hprog[LL * NQUAD];          // scan progress (t steps done)
__device__ int   g_xprog[LL * NQUAD];          // xp rows available for layer l
__device__ int   g_task;                        // dynamic task counter

// scan smem: h buffers [2 buf][4 samples][260 fl] = 8320B, then per-thread W
// (32 f4 data + 1 f4 pad = 132 fl stride -> 4-wf private reads, the floor).
// proj smem: Ash 128x17 @0, Bsh 16x132 @8704 (overlaid; tasks serialized).
#define SAMP_STRIDE 260               // 256 + 4 pad between kh halves
#define BUF_STRIDE  (4 * SAMP_STRIDE) // 1040
#define SM_W_OFF    8320
#define SM_W_STRIDE 132
#define SMEM_DYN    (SM_W_OFF + 256 * SM_W_STRIDE * 4)   // 143488

// ---------------------------------------------------------------------------
__device__ __forceinline__ void ffma2(float2& c, float2 a, float2 b) {
    union U { float2 f; unsigned long long u; };
    U A, Bv, C;
    A.f = a; Bv.f = b; C.f = c;
    asm("fma.rn.f32x2 %0, %1, %2, %3;"
        : "=l"(C.u) : "l"(A.u), "l"(Bv.u), "l"(C.u));
    c = C.f;
}

// ---------------------------------------------------------------------------
// Layer-0 projection + watermark/counter reset: xp = x*W0 + b0 (I==1)
// ---------------------------------------------------------------------------
__global__ void proj0_kernel(const float* __restrict__ x,
                             const float* __restrict__ W0,
                             const float* __restrict__ b0) {
    int row = blockIdx.x;
    int j   = threadIdx.x;
    if (j == 0 && row < LL * NQUAD) {           // replay-safe reset
        g_hprog[row] = 0;
        g_xprog[row] = (row < NQUAD) ? TT : 0;  // layer-0 xp filled here
        if (row == 0) g_task = 0;
    }
    g_xp[(size_t)row * HH + j] = x[row] * W0[j] + b0[j];
}

// ---------------------------------------------------------------------------
// Persistent wavefront kernel. 147 CTAs x 256 threads, dynamic task grab.
// Task q: l = q>>6, r = q&63, c = r>>1 (quad id), r&1 -> proj.
// Deps point to strictly smaller q; counter grab is monotone -> no deadlock.
// ---------------------------------------------------------------------------
__global__ __launch_bounds__(256, 1)
void wave_kernel(const float* __restrict__ Whh,
                 const float* __restrict__ bhh,
                 const float* __restrict__ Wih,
                 const float* __restrict__ bih) {
    extern __shared__ __align__(16) char smem_raw[];
    __shared__ int s_q;
    const int tid = threadIdx.x;

    for (;;) {
        if (tid == 0) s_q = atomicAdd(&g_task, 1);
        __syncthreads();
        const int q = s_q;
        __syncthreads();               // everyone read s_q before next overwrite
        if (q >= NTASK) break;

        const int l = q >> 6;
        const int r = q & 63;
        const int c = r >> 1;          // quad id 0..31

        if ((r & 1) == 0) {
            // ===================== SCAN(l, c): samples 4c..4c+3 =====================
            // Thread (j2 = tid>>1, kh = tid&1): cols c0 = 2*j2, c0+1;
            // k in [kh*128, +128). W row c0 in regs (32 f4), row c0+1 in
            // private smem (32 f4). FMA 2048 == crossbar 2048 per step/SM.
            float* sm_h = (float*)smem_raw;
            float* myw  = (float*)(smem_raw + SM_W_OFF) + tid * SM_W_STRIDE;

            const int j2 = tid >> 1;
            const int kh = tid & 1;
            const int c0 = 2 * j2;
            const int k0 = kh * 128;

            const float* W0r = Whh + ((size_t)l * HH + c0) * HH + k0;
            const float* W1r = W0r + HH;

            float4 wr[32];
#pragma unroll
            for (int i = 0; i < 32; i++) wr[i] = *(const float4*)(W0r + 4 * i);
#pragma unroll
            for (int i = 0; i < 32; i++)
                *(float4*)(myw + 4 * i) = *(const float4*)(W1r + 4 * i);

            float2 bj = make_float2(0.f, 0.f);
            if (kh == 0) bj = *(const float2*)(bhh + l * HH + c0);

            for (int i = tid; i < 2 * BUF_STRIDE; i += 256) sm_h[i] = 0.0f;
            __syncthreads();

            const float* xp[4];
            float*       ho[4];
#pragma unroll
            for (int s = 0; s < 4; s++) {
                xp[s] = g_xp + (size_t)(4 * c + s) * TT * HH + c0;
                ho[s] = g_h  + (size_t)(4 * c + s) * TT * HH + c0;
            }

            const int rdo   = kh * 132;                 // read base within sample
            const int wslot = c0 + (c0 >= 128 ? 4 : 0); // write offset

            int cur = 0;
            for (int ch = 0; ch < NCHUNK; ch++) {
                if (tid == 0) {
                    const int need = (ch + 1) * CHUNK;
                    while (((volatile int*)g_xprog)[l * NQUAD + c] < need)
                        __nanosleep(200);
                }
                __syncthreads();
                __threadfence();   // acquire: order xp reads after flag

#pragma unroll 1
                for (int tt = 0; tt < CHUNK; tt++) {
                    float2 xv[4];
                    if (kh == 0) {
#pragma unroll
                        for (int s = 0; s < 4; s++) xv[s] = *(const float2*)xp[s];
                    }
#pragma unroll
                    for (int s = 0; s < 4; s++) xp[s] += HH;

                    const float* hb = sm_h + cur * BUF_STRIDE + rdo;

                    float2 aA[2][4], aB[2][4];   // [row][sample]
#pragma unroll
                    for (int rr = 0; rr < 2; rr++)
#pragma unroll
                        for (int s = 0; s < 4; s++) {
                            aA[rr][s] = make_float2(0.f, 0.f);
                            aB[rr][s] = make_float2(0.f, 0.f);
                        }

#pragma unroll
                    for (int i = 0; i < 32; i++) {
                        float4 w0 = wr[i];
                        float4 w1 = *(const float4*)(myw + 4 * i);
#pragma unroll
                        for (int s = 0; s < 4; s++) {
                            float4 h = *(const float4*)(hb + s * SAMP_STRIDE + 4 * i);
                            ffma2(aA[0][s], make_float2(w0.x, w0.y), make_float2(h.x, h.y));
                            ffma2(aB[0][s], make_float2(w0.z, w0.w), make_float2(h.z, h.w));
                            ffma2(aA[1][s], make_float2(w1.x, w1.y), make_float2(h.x, h.y));
                            ffma2(aB[1][s], make_float2(w1.z, w1.w), make_float2(h.z, h.w));
                        }
                    }

                    float v[2][4];
#pragma unroll
                    for (int rr = 0; rr < 2; rr++)
#pragma unroll
                        for (int s = 0; s < 4; s++) {
                            float t2 = (aA[rr][s].x + aA[rr][s].y)
                                     + (aB[rr][s].x + aB[rr][s].y);
                            t2 += __shfl_down_sync(0xffffffffu, t2, 1, 2);
                            v[rr][s] = t2;
                        }

                    int nxt = cur ^ 1;
                    if (kh == 0) {
#pragma unroll
                        for (int s = 0; s < 4; s++) {
                            float2 o;
                            o.x = fmaxf(xv[s].x + bj.x + v[0][s], 0.f);
                            o.y = fmaxf(xv[s].y + bj.y + v[1][s], 0.f);
                            *(float2*)(sm_h + nxt * BUF_STRIDE + s * SAMP_STRIDE + wslot) = o;
                            *(float2*)ho[s] = o;
                        }
                    }
#pragma unroll
                    for (int s = 0; s < 4; s++) ho[s] += HH;
                    __syncthreads();   // h(t) ready for step t+1
                    cur = nxt;
                }

                __threadfence();       // each thread fences its own h STGs
                __syncthreads();
                if (tid == 0)
                    ((volatile int*)g_hprog)[l * NQUAD + c] = (ch + 1) * CHUNK;
            }
        } else if (l < LL - 1) {
            // ===================== PROJ(l, c): h^l -> xp^{l+1} =====================
            float (*Ash)[17]  = (float(*)[17])smem_raw;
            float (*Bsh)[132] = (float(*)[132])(smem_raw + 8704);

            const float* Bw   = Wih + (size_t)l * HH * HH;
            const float* bias = bih + (size_t)l * HH;

            const int tx = tid & 15;      // 8 cols each
            const int ty = tid >> 4;      // 8 rows each

            for (int ch = 0; ch < NCHUNK; ch++) {
                if (tid == 0) {
                    const int need = (ch + 1) * CHUNK;
                    while (((volatile int*)g_hprog)[l * NQUAD + c] < need)
                        __nanosleep(200);
                }
                __syncthreads();
                __threadfence();   // acquire: order h reads after flag

#pragma unroll 1
                for (int sub = 0; sub < 8; sub++) {
                    const int s  = sub >> 1;                      // sample 0..3
                    const int cb = (sub & 1) * 128;               // col tile
                    const size_t rowbase = (size_t)(4 * c + s) * TT + ch * CHUNK;

                    float2 acc[8][4];
#pragma unroll
                    for (int i = 0; i < 8; i++)
#pragma unroll
                        for (int jp = 0; jp < 4; jp++) acc[i][jp] = make_float2(0.f, 0.f);

                    for (int kt = 0; kt < HH; kt += 16) {
#pragma unroll
                        for (int p = 0; p < 8; p++) {
                            int f = tid + p * 256;
                            int m = f >> 4, k = f & 15;
                            Ash[m][k] = (m < CHUNK)
                                ? g_h[(rowbase + m) * HH + kt + k] : 0.0f;
                        }
#pragma unroll
                        for (int p = 0; p < 8; p++) {
                            int f = tid + p * 256;
                            int n = f >> 4, k = f & 15;
                            Bsh[k][n] = Bw[(size_t)(cb + n) * HH + kt + k];
                        }
                        __syncthreads();
#pragma unroll
                        for (int kk = 0; kk < 16; kk++) {
                            float4 bv0 = *(const float4*)&Bsh[kk][tx * 8];
                            float4 bv1 = *(const float4*)&Bsh[kk][tx * 8 + 4];
                            float2 bp[4] = { {bv0.x, bv0.y}, {bv0.z, bv0.w},
                                             {bv1.x, bv1.y}, {bv1.z, bv1.w} };
#pragma unroll
                            for (int i = 0; i < 8; i++) {
                                float av = Ash[ty * 8 + i][kk];
                                float2 aa = {av, av};
#pragma unroll
                                for (int jp = 0; jp < 4; jp++)
                                    ffma2(acc[i][jp], aa, bp[jp]);
                            }
                        }
                        __syncthreads();
                    }

                    float bjv[8];
#pragma unroll
                    for (int jj = 0; jj < 8; jj++) bjv[jj] = bias[cb + tx * 8 + jj];
#pragma unroll
                    for (int i = 0; i < 8; i++) {
                        int m = ty * 8 + i;
                        if (m < CHUNK) {
#pragma unroll
                            for (int jp = 0; jp < 4; jp++) {
                                g_xp[(rowbase + m) * HH + cb + tx * 8 + 2 * jp]     = acc[i][jp].x + bjv[2 * jp];
                                g_xp[(rowbase + m) * HH + cb + tx * 8 + 2 * jp + 1] = acc[i][jp].y + bjv[2 * jp + 1];
                            }
                        }
                    }
                }

                __threadfence();
                __syncthreads();
                if (tid == 0)
                    ((volatile int*)g_xprog)[(l + 1) * NQUAD + c] = (ch + 1) * CHUNK;
            }
        }
        __syncthreads();   // smem reuse barrier between tasks
    }
}

// ---------------------------------------------------------------------------
// Final FC: out[b,c] = sum_k h[b,T-1,k]*W_fc[c,k] + b_fc[c]
// ---------------------------------------------------------------------------
__global__ void fc_kernel(const float* __restrict__ Wfc,
                          const float* __restrict__ bfc,
                          float* __restrict__ out) {
    int b   = blockIdx.x;
    int tid = threadIdx.x;
    __shared__ float red[8];
    float hv = g_h[((size_t)b * TT + (TT - 1)) * HH + tid];
#pragma unroll
    for (int c = 0; c < CC; c++) {
        float p = hv * Wfc[(size_t)c * HH + tid];
#pragma unroll
        for (int o = 16; o > 0; o >>= 1)
            p += __shfl_down_sync(0xffffffffu, p, o);
        if ((tid & 31) == 0) red[tid >> 5] = p;
        __syncthreads();
        if (tid == 0) {
            float s = 0.0f;
#pragma unroll
            for (int w = 0; w < 8; w++) s += red[w];
            out[b * CC + c] = s + bfc[c];
        }
        __syncthreads();
    }
}

// ---------------------------------------------------------------------------
extern "C" void kernel_launch(void* const* d_in, const int* in_sizes, int n_in,
                              void* d_out, int out_size) {
    const float* x      = (const float*)d_in[0];
    const float* W_ih0  = (const float*)d_in[1];
    const float* b_ih0  = (const float*)d_in[2];
    const float* W_ih   = (const float*)d_in[3];
    const float* b_ih   = (const float*)d_in[4];
    const float* W_hh   = (const float*)d_in[5];
    const float* b_hh   = (const float*)d_in[6];
    const float* W_fc   = (const float*)d_in[7];
    const float* b_fc   = (const float*)d_in[8];
    float*       out    = (float*)d_out;

    static int smem_set = 0;
    if (!smem_set) {
        cudaFuncSetAttribute(wave_kernel,
                             cudaFuncAttributeMaxDynamicSharedMemorySize, SMEM_DYN);
        smem_set = 1;
    }

    proj0_kernel<<<BB * TT, HH>>>(x, W_ih0, b_ih0);
    wave_kernel<<<NCTA, 256, SMEM_DYN>>>(W_hh, b_hh, W_ih, b_ih);
    fc_kernel<<<BB, HH>>>(W_fc, b_fc, out);
}